// round 4
// baseline (speedup 1.0000x reference)
#include <cuda_runtime.h>
#include <cstdint>

// FRIENDATTN single persistent double-buffered kernel.
// Per friend-row n (N=16384): scores = x[n]·self[n/64] (L=50,D=128),
// w = softmax(scores); out[n] = sum_l w[l]*mask[n,l]*x[n,l,:].
//
// 25.6KB row tiles staged via cp.async.cg (L1 bypass), 2-stage double buffer,
// persistent CTAs. Mask dtype (u8 bool / int32 / int64) detected inline per CTA
// from the first 8KB (deterministic, L2-cached); mask rows read directly from
// global by the softmax warp, issued early so latency hides under the pipeline.

#define D_DIM 128
#define L_DIM 50
#define TPB   128
#define NROWS (256 * 64)
#define GRID  608            // 152 SMs * 4 CTAs/SM

// dynamic SMEM layout (floats):
//  sx     [2][6400]   @ 0
//  sself  [2][128]    @ 12800
//  sscore [64]        @ 13056
//  sw     [64]        @ 13120
#define SM_FLOATS 13184
#define OFF_SELF  12800
#define OFF_SCORE 13056
#define OFF_W     13120

__device__ __forceinline__ void cp_async16(float* smem_dst, const float4* gmem_src)
{
    unsigned int s = (unsigned int)__cvta_generic_to_shared(smem_dst);
    asm volatile("cp.async.cg.shared.global [%0], [%1], 16;\n" :: "r"(s), "l"(gmem_src));
}

__global__ __launch_bounds__(TPB) void friendattn_kernel(
    const float* __restrict__ x,        // [N, L, D]
    const float* __restrict__ self_x,   // [B, D]
    const void*  __restrict__ mask,     // [N, L]; dtype detected inline
    float* __restrict__ out)            // [N, D]
{
    extern __shared__ float smem[];
    const int tid  = threadIdx.x;
    const int lane = tid & 31;
    const int warp = tid >> 5;

    // ---- inline mask dtype detection (first 2048 int32 words = 8KB) ----
    // u8 bool packed: some word > 1 (P[miss] ~ 8^-2048).
    // int64: words in {0,1} but all odd (high) words zero.
    // int32: words in {0,1}, odd words nonzero somewhere.
    int gt1 = 0, odd_nz = 0, even_nz = 0;
    {
        const int* mw = (const int*)mask;
        #pragma unroll
        for (int it = 0; it < 16; ++it) {
            unsigned int v = (unsigned int)mw[it * TPB + tid];
            int i = it * TPB + tid;
            if (v > 1u) gt1 = 1;
            if (v != 0u) { if (i & 1) odd_nz = 1; else even_nz = 1; }
        }
    }
    const int any_gt1  = __syncthreads_or(gt1);
    const int any_odd  = __syncthreads_or(odd_nz);
    const int any_even = __syncthreads_or(even_nz);
    const int mode = any_gt1 ? 0 : ((!any_odd && any_even) ? 2 : 1);

    // ---- prefetch helper ----
    auto prefetch = [&](int row, int buf) {
        float* sx = smem + buf * (L_DIM * D_DIM);
        const float4* xrow = (const float4*)(x + (size_t)row * (L_DIM * D_DIM));
        #pragma unroll
        for (int it = 0; it < 12; ++it)
            cp_async16(sx + (it * TPB + tid) * 4, xrow + it * TPB + tid);
        if (tid < 64)
            cp_async16(sx + (12 * TPB + tid) * 4, xrow + 12 * TPB + tid);
        if (tid < 32)
            cp_async16(smem + OFF_SELF + buf * D_DIM + tid * 4,
                       (const float4*)(self_x + (size_t)(row >> 6) * D_DIM) + tid);
    };

    int row = blockIdx.x;
    if (row < NROWS) prefetch(row, 0);
    asm volatile("cp.async.commit_group;\n" ::: "memory");

    int buf = 0;
    while (row < NROWS) {
        const int nxt = row + GRID;
        if (nxt < NROWS) prefetch(nxt, buf ^ 1);
        asm volatile("cp.async.commit_group;\n" ::: "memory");

        // ---- softmax warp issues mask loads early (overlap with wait) ----
        float fm0 = 0.0f, fm1 = 0.0f;
        if (warp == 0) {
            const long long mbase = (long long)row * L_DIM;
            if (mode == 0) {
                const unsigned char* m = (const unsigned char*)mask + mbase;
                fm0 = m[lane] ? 1.0f : 0.0f;
                if (lane + 32 < L_DIM) fm1 = m[lane + 32] ? 1.0f : 0.0f;
            } else if (mode == 1) {
                const int* m = (const int*)mask + mbase;
                fm0 = m[lane] ? 1.0f : 0.0f;
                if (lane + 32 < L_DIM) fm1 = m[lane + 32] ? 1.0f : 0.0f;
            } else {
                const int* m = (const int*)mask + 2 * mbase;
                fm0 = m[2 * lane] ? 1.0f : 0.0f;
                if (lane + 32 < L_DIM) fm1 = m[2 * (lane + 32)] ? 1.0f : 0.0f;
            }
        }

        // wait until only the newest group is still in flight
        asm volatile("cp.async.wait_group 1;\n" ::: "memory");
        __syncthreads();

        const float* sx    = smem + buf * (L_DIM * D_DIM);
        const float* sself = smem + OFF_SELF + buf * D_DIM;
        float* sscore = smem + OFF_SCORE;
        float* sw     = smem + OFF_W;

        // ---- scores: warp w handles l = w, w+4, ... ----
        const float4 s4 = ((const float4*)sself)[lane];
        for (int l = warp; l < L_DIM; l += 4) {
            float4 v = ((const float4*)(sx + l * D_DIM))[lane];
            float p = v.x * s4.x + v.y * s4.y + v.z * s4.z + v.w * s4.w;
            #pragma unroll
            for (int o = 16; o > 0; o >>= 1) p += __shfl_xor_sync(0xffffffffu, p, o);
            if (lane == 0) sscore[l] = p;
        }
        __syncthreads();

        // ---- softmax over L=50, mask folded in (warp 0) ----
        if (warp == 0) {
            float v0 = sscore[lane];
            float v1 = (lane + 32 < L_DIM) ? sscore[lane + 32] : -3.0e38f;
            float mx = fmaxf(v0, v1);
            #pragma unroll
            for (int o = 16; o > 0; o >>= 1) mx = fmaxf(mx, __shfl_xor_sync(0xffffffffu, mx, o));
            float e0 = __expf(v0 - mx);
            float e1 = (lane + 32 < L_DIM) ? __expf(v1 - mx) : 0.0f;
            float s = e0 + e1;
            #pragma unroll
            for (int o = 16; o > 0; o >>= 1) s += __shfl_xor_sync(0xffffffffu, s, o);
            float inv = 1.0f / s;
            sw[lane] = e0 * inv * fm0;
            if (lane + 32 < L_DIM) sw[lane + 32] = e1 * inv * fm1;
        }
        __syncthreads();

        // ---- weighted pooling: thread tid owns output dim d=tid ----
        float acc = 0.0f;
        #pragma unroll
        for (int l = 0; l < L_DIM; ++l)
            acc = fmaf(sw[l], sx[l * D_DIM + tid], acc);
        out[(size_t)row * D_DIM + tid] = acc;

        __syncthreads();   // protect sscore/sw + sx[buf] reuse next iteration
        buf ^= 1;
        row = nxt;
    }
}

extern "C" void kernel_launch(void* const* d_in, const int* in_sizes, int n_in,
                              void* d_out, int out_size)
{
    const float* x      = (const float*)d_in[0];
    const float* self_x = (const float*)d_in[1];
    const void*  mask   = d_in[n_in - 1];
    float* out = (float*)d_out;

    cudaFuncSetAttribute(friendattn_kernel,
                         cudaFuncAttributeMaxDynamicSharedMemorySize,
                         SM_FLOATS * sizeof(float));

    friendattn_kernel<<<GRID, TPB, SM_FLOATS * sizeof(float)>>>(x, self_x, mask, out);
}

// round 5
// speedup vs baseline: 1.0964x; 1.0964x over previous
#include <cuda_runtime.h>
#include <cstdint>

// FRIENDATTN persistent kernel, TMA bulk-copy double-buffered pipeline.
// Per friend-row n (N=16384): scores = x[n]·self[n/64] (L=50,D=128),
// w = softmax(scores); out[n] = sum_l w[l]*mask[n,l]*x[n,l,:].
//
// Row tile (25600B) + self vector (512B) fetched with TWO cp.async.bulk ops
// per row (vs 1600 LDGSTS) -> removes the LSU issue bottleneck seen in R4.
// mbarrier complete_tx tracks arrival; 2-stage buffer, 4 CTAs/SM.

#define D_DIM 128
#define L_DIM 50
#define TPB   128
#define NROWS (256 * 64)
#define GRID  608            // 152 SMs * 4 CTAs/SM

#define TILE_BYTES  (L_DIM * D_DIM * 4)   // 25600
#define SELF_BYTES  (D_DIM * 4)           // 512
#define TX_BYTES    (TILE_BYTES + SELF_BYTES)

// dynamic SMEM layout (float index):
//  sx     [2][6400]   @ 0        (offsets 0 / 25600B, 16B aligned)
//  sself  [2][128]    @ 12800
//  sscore [64]        @ 13056
//  sw     [64]        @ 13120
//  mbar   [2] u64     @ 13184    (byte 52736, 8B aligned)
#define OFF_SELF   12800
#define OFF_SCORE  13056
#define OFF_W      13120
#define OFF_MBAR   13184
#define SM_FLOATS  13192

__device__ __forceinline__ unsigned int smem_u32(const void* p)
{
    return (unsigned int)__cvta_generic_to_shared(p);
}

__device__ __forceinline__ void mbar_init(unsigned int mbar, unsigned int count)
{
    asm volatile("mbarrier.init.shared.b64 [%0], %1;" :: "r"(mbar), "r"(count) : "memory");
}
__device__ __forceinline__ void mbar_expect_tx(unsigned int mbar, unsigned int bytes)
{
    asm volatile("mbarrier.arrive.expect_tx.shared.b64 _, [%0], %1;"
                 :: "r"(mbar), "r"(bytes) : "memory");
}
__device__ __forceinline__ void mbar_wait(unsigned int mbar, unsigned int phase)
{
    asm volatile(
        "{\n\t"
        ".reg .pred P;\n\t"
        "W%=:\n\t"
        "mbarrier.try_wait.parity.acquire.cta.shared::cta.b64 P, [%0], %1, 0x989680;\n\t"
        "@!P bra W%=;\n\t"
        "}"
        :: "r"(mbar), "r"(phase) : "memory");
}
__device__ __forceinline__ void bulk_g2s(unsigned int dst, const void* src,
                                         unsigned int bytes, unsigned int mbar)
{
    asm volatile(
        "cp.async.bulk.shared::cta.global.mbarrier::complete_tx::bytes [%0], [%1], %2, [%3];"
        :: "r"(dst), "l"(src), "r"(bytes), "r"(mbar) : "memory");
}

__global__ __launch_bounds__(TPB) void friendattn_kernel(
    const float* __restrict__ x,        // [N, L, D]
    const float* __restrict__ self_x,   // [B, D]
    const void*  __restrict__ mask,     // [N, L]; dtype detected inline
    float* __restrict__ out)            // [N, D]
{
    extern __shared__ float smem[];
    const int tid  = threadIdx.x;
    const int lane = tid & 31;
    const int warp = tid >> 5;

    const unsigned int mbar0 = smem_u32(smem + OFF_MBAR);
    const unsigned int mbar1 = mbar0 + 8;

    // ---- inline mask dtype detection (first 2048 int32 words = 8KB, L2-hot) ----
    int gt1 = 0, odd_nz = 0, even_nz = 0;
    {
        const int* mw = (const int*)mask;
        #pragma unroll
        for (int it = 0; it < 16; ++it) {
            int i = it * TPB + tid;
            unsigned int v = (unsigned int)mw[i];
            if (v > 1u) gt1 = 1;
            if (v != 0u) { if (i & 1) odd_nz = 1; else even_nz = 1; }
        }
    }
    const int any_gt1  = __syncthreads_or(gt1);
    const int any_odd  = __syncthreads_or(odd_nz);
    const int any_even = __syncthreads_or(even_nz);
    const int mode = any_gt1 ? 0 : ((!any_odd && any_even) ? 2 : 1);

    if (tid == 0) {
        mbar_init(mbar0, 1);
        mbar_init(mbar1, 1);
        asm volatile("fence.proxy.async.shared::cta;" ::: "memory");
    }
    __syncthreads();

    // ---- TMA prefetch: one bulk copy for tile, one for self vector ----
    auto prefetch = [&](int row, int buf) {
        const unsigned int mb = buf ? mbar1 : mbar0;
        mbar_expect_tx(mb, TX_BYTES);
        bulk_g2s(smem_u32(smem + buf * (L_DIM * D_DIM)),
                 x + (size_t)row * (L_DIM * D_DIM), TILE_BYTES, mb);
        bulk_g2s(smem_u32(smem + OFF_SELF + buf * D_DIM),
                 self_x + (size_t)(row >> 6) * D_DIM, SELF_BYTES, mb);
    };

    int row = blockIdx.x;
    if (tid == 0 && row < NROWS) prefetch(row, 0);

    int buf = 0;
    unsigned int phase[2] = {0u, 0u};

    while (row < NROWS) {
        const int nxt = row + GRID;
        if (tid == 0 && nxt < NROWS) prefetch(nxt, buf ^ 1);

        // ---- softmax warp issues mask loads early (overlap with wait) ----
        float fm0 = 0.0f, fm1 = 0.0f;
        if (warp == 0) {
            const long long mbase = (long long)row * L_DIM;
            if (mode == 0) {
                const unsigned char* m = (const unsigned char*)mask + mbase;
                fm0 = m[lane] ? 1.0f : 0.0f;
                if (lane + 32 < L_DIM) fm1 = m[lane + 32] ? 1.0f : 0.0f;
            } else if (mode == 1) {
                const int* m = (const int*)mask + mbase;
                fm0 = m[lane] ? 1.0f : 0.0f;
                if (lane + 32 < L_DIM) fm1 = m[lane + 32] ? 1.0f : 0.0f;
            } else {
                const int* m = (const int*)mask + 2 * mbase;
                fm0 = m[2 * lane] ? 1.0f : 0.0f;
                if (lane + 32 < L_DIM) fm1 = m[2 * (lane + 32)] ? 1.0f : 0.0f;
            }
        }

        // ---- wait for this buffer's TMA ----
        mbar_wait(buf ? mbar1 : mbar0, phase[buf]);
        phase[buf] ^= 1u;

        const float* sx    = smem + buf * (L_DIM * D_DIM);
        const float* sself = smem + OFF_SELF + buf * D_DIM;
        float* sscore = smem + OFF_SCORE;
        float* sw     = smem + OFF_W;

        // ---- scores: warp w handles l = w, w+4, ... ----
        const float4 s4 = ((const float4*)sself)[lane];
        for (int l = warp; l < L_DIM; l += 4) {
            float4 v = ((const float4*)(sx + l * D_DIM))[lane];
            float p = v.x * s4.x + v.y * s4.y + v.z * s4.z + v.w * s4.w;
            #pragma unroll
            for (int o = 16; o > 0; o >>= 1) p += __shfl_xor_sync(0xffffffffu, p, o);
            if (lane == 0) sscore[l] = p;
        }
        __syncthreads();

        // ---- softmax over L=50, mask folded in (warp 0) ----
        if (warp == 0) {
            float v0 = sscore[lane];
            float v1 = (lane + 32 < L_DIM) ? sscore[lane + 32] : -3.0e38f;
            float mx = fmaxf(v0, v1);
            #pragma unroll
            for (int o = 16; o > 0; o >>= 1) mx = fmaxf(mx, __shfl_xor_sync(0xffffffffu, mx, o));
            float e0 = __expf(v0 - mx);
            float e1 = (lane + 32 < L_DIM) ? __expf(v1 - mx) : 0.0f;
            float s = e0 + e1;
            #pragma unroll
            for (int o = 16; o > 0; o >>= 1) s += __shfl_xor_sync(0xffffffffu, s, o);
            float inv = 1.0f / s;
            sw[lane] = e0 * inv * fm0;
            if (lane + 32 < L_DIM) sw[lane + 32] = e1 * inv * fm1;
        }
        __syncthreads();

        // ---- weighted pooling: thread tid owns output dim d=tid ----
        float acc = 0.0f;
        #pragma unroll
        for (int l = 0; l < L_DIM; ++l)
            acc = fmaf(sw[l], sx[l * D_DIM + tid], acc);
        out[(size_t)row * D_DIM + tid] = acc;

        __syncthreads();   // all reads of sx[buf]/sw done before tid0 refills next iter
        buf ^= 1;
        row = nxt;
    }
}

extern "C" void kernel_launch(void* const* d_in, const int* in_sizes, int n_in,
                              void* d_out, int out_size)
{
    const float* x      = (const float*)d_in[0];
    const float* self_x = (const float*)d_in[1];
    const void*  mask   = d_in[n_in - 1];
    float* out = (float*)d_out;

    cudaFuncSetAttribute(friendattn_kernel,
                         cudaFuncAttributeMaxDynamicSharedMemorySize,
                         SM_FLOATS * sizeof(float));

    friendattn_kernel<<<GRID, TPB, SM_FLOATS * sizeof(float)>>>(x, self_x, mask, out);
}